// round 2
// baseline (speedup 1.0000x reference)
#include <cuda_runtime.h>
#include <cuda_bf16.h>

#define NN 100000
#define EE 1600000
#define IC 128
#define OC 128      // OUT_C * HEADS
#define NEG_SLOPE 0.2f

// ---------------- device scratch (no allocations allowed) ----------------
__device__ float g_xproj[(size_t)NN * OC];     // 51.2 MB, fits in L2
__device__ float g_al[NN * 4];
__device__ float g_ar[NN * 4];
__device__ int   g_deg[NN];
__device__ int   g_rowptr[NN + 1];
__device__ int   g_cursor[NN];
__device__ int   g_csrcol[EE];
__device__ int   g_bsums[128];

// ---------------- zero degree counters (scratch persists across replays) ----
__global__ void zero_deg_k() {
    int i = blockIdx.x * blockDim.x + threadIdx.x;
    if (i < NN) g_deg[i] = 0;
}

// ---------------- fp32 SGEMM: x[M,128] @ W[128,128]^T -> g_xproj[M,128] -----
// 128x128 block tile, 256 threads, 8x8 register tile per thread.
__global__ __launch_bounds__(256) void sgemm128_k(const float* __restrict__ x,
                                                  const float* __restrict__ W) {
    __shared__ float As[16][128];   // As[k][m]
    __shared__ float Bs[16][128];   // Bs[k][n]  (n = W row)
    const int tid = threadIdx.x;
    const int bm0 = blockIdx.x * 128;
    const int tn = tid & 15;        // 0..15 -> 8 cols each
    const int tm = tid >> 4;        // 0..15 -> 8 rows each

    float acc[8][8];
#pragma unroll
    for (int i = 0; i < 8; i++)
#pragma unroll
        for (int j = 0; j < 8; j++) acc[i][j] = 0.f;

    for (int kb = 0; kb < 128; kb += 16) {
#pragma unroll
        for (int q = 0; q < 2; q++) {
            int idx = tid * 2 + q;          // 0..511
            int m = idx >> 2;               // 0..127
            int k4 = (idx & 3) << 2;        // 0,4,8,12
            float4 v = make_float4(0.f, 0.f, 0.f, 0.f);
            if (bm0 + m < NN)
                v = *(const float4*)(x + (size_t)(bm0 + m) * 128 + kb + k4);
            As[k4 + 0][m] = v.x; As[k4 + 1][m] = v.y;
            As[k4 + 2][m] = v.z; As[k4 + 3][m] = v.w;
            float4 w = *(const float4*)(W + (size_t)m * 128 + kb + k4);
            Bs[k4 + 0][m] = w.x; Bs[k4 + 1][m] = w.y;
            Bs[k4 + 2][m] = w.z; Bs[k4 + 3][m] = w.w;
        }
        __syncthreads();
#pragma unroll
        for (int kk = 0; kk < 16; kk++) {
            float a[8], b[8];
            *(float4*)(a)     = *(const float4*)&As[kk][tm * 8];
            *(float4*)(a + 4) = *(const float4*)&As[kk][tm * 8 + 4];
            *(float4*)(b)     = *(const float4*)&Bs[kk][tn * 8];
            *(float4*)(b + 4) = *(const float4*)&Bs[kk][tn * 8 + 4];
#pragma unroll
            for (int i = 0; i < 8; i++)
#pragma unroll
                for (int j = 0; j < 8; j++) acc[i][j] += a[i] * b[j];
        }
        __syncthreads();
    }

#pragma unroll
    for (int i = 0; i < 8; i++) {
        int r = bm0 + tm * 8 + i;
        if (r < NN) {
            float* dst = g_xproj + (size_t)r * 128 + tn * 8;
            *(float4*)(dst)     = make_float4(acc[i][0], acc[i][1], acc[i][2], acc[i][3]);
            *(float4*)(dst + 4) = make_float4(acc[i][4], acc[i][5], acc[i][6], acc[i][7]);
        }
    }
}

// ---------------- per-node attention logits: alpha_l/alpha_r [N,4] ----------
// one warp per node; lane l covers columns 4l..4l+3 (head = l>>3)
__global__ void alpha_k(const float* __restrict__ attl, const float* __restrict__ attr) {
    int warp = (blockIdx.x * blockDim.x + threadIdx.x) >> 5;
    int lane = threadIdx.x & 31;
    if (warp >= NN) return;
    float4 v  = *(const float4*)(g_xproj + (size_t)warp * 128 + lane * 4);
    float4 al = *(const float4*)(attl + lane * 4);
    float4 ar = *(const float4*)(attr + lane * 4);
    float sl = v.x * al.x + v.y * al.y + v.z * al.z + v.w * al.w;
    float sr = v.x * ar.x + v.y * ar.y + v.z * ar.z + v.w * ar.w;
#pragma unroll
    for (int o = 1; o < 8; o <<= 1) {
        sl += __shfl_xor_sync(0xffffffffu, sl, o);
        sr += __shfl_xor_sync(0xffffffffu, sr, o);
    }
    if ((lane & 7) == 0) {
        g_al[warp * 4 + (lane >> 3)] = sl;
        g_ar[warp * 4 + (lane >> 3)] = sr;
    }
}

// ---------------- CSR build: histogram, scan, scatter -----------------------
// edge_index passed as int32 (harness downcasts the reference's int64).
__global__ void deg_k(const int* __restrict__ ei) {
    int e = blockIdx.x * blockDim.x + threadIdx.x;
    if (e < EE) {
        int r = ei[e];
        if ((unsigned)r < NN) atomicAdd(&g_deg[r], 1);
    }
}

__global__ __launch_bounds__(1024) void scan1_k() {
    int b = blockIdx.x, t = threadIdx.x;
    int i = b * 1024 + t;
    int v = (i < NN) ? g_deg[i] : 0;
    int lane = t & 31, wid = t >> 5;
    int inc = v;
#pragma unroll
    for (int o = 1; o < 32; o <<= 1) {
        int u = __shfl_up_sync(0xffffffffu, inc, o);
        if (lane >= o) inc += u;
    }
    __shared__ int ws[32];
    if (lane == 31) ws[wid] = inc;
    __syncthreads();
    if (wid == 0) {
        int wv = ws[lane];
        int wi = wv;
#pragma unroll
        for (int o = 1; o < 32; o <<= 1) {
            int u = __shfl_up_sync(0xffffffffu, wi, o);
            if (lane >= o) wi += u;
        }
        ws[lane] = wi - wv;              // exclusive warp offsets
        if (lane == 31) g_bsums[b] = wi; // block total
    }
    __syncthreads();
    int excl = ws[wid] + inc - v;
    if (i < NN) g_rowptr[i] = excl;      // partial (needs block offset)
}

__global__ void scan2_k(int nb) {
    int t = threadIdx.x;                 // 128 threads
    int v = (t < nb) ? g_bsums[t] : 0;
    int lane = t & 31, wid = t >> 5;
    int inc = v;
#pragma unroll
    for (int o = 1; o < 32; o <<= 1) {
        int u = __shfl_up_sync(0xffffffffu, inc, o);
        if (lane >= o) inc += u;
    }
    __shared__ int ws[4];
    if (lane == 31) ws[wid] = inc;
    __syncthreads();
    int off = 0;
    for (int w = 0; w < wid; w++) off += ws[w];
    if (t < nb) g_bsums[t] = off + inc - v;   // exclusive
}

__global__ void scan3_k() {
    int i = blockIdx.x * blockDim.x + threadIdx.x;
    if (i < NN) {
        int v = g_rowptr[i] + g_bsums[i >> 10];
        g_rowptr[i] = v;
        g_cursor[i] = v;
    }
    if (i == 0) g_rowptr[NN] = EE;
}

__global__ void scatter_k(const int* __restrict__ ei) {
    int e = blockIdx.x * blockDim.x + threadIdx.x;
    if (e < EE) {
        int r = ei[e];
        int c = ei[EE + e];
        if ((unsigned)r < NN && (unsigned)c < NN) {
            int p = atomicAdd(&g_cursor[r], 1);
            if ((unsigned)p < EE) g_csrcol[p] = c;
        }
    }
}

// ---------------- fused softmax + weighted aggregation ----------------------
// one warp per destination node; numerator + denominator in one pass.
__global__ __launch_bounds__(256) void agg_k(const float* __restrict__ bias,
                                             float* __restrict__ out) {
    int warp = (blockIdx.x * blockDim.x + threadIdx.x) >> 5;
    int lane = threadIdx.x & 31;
    if (warp >= NN) return;
    int h = lane >> 3;
    float aln = g_al[warp * 4 + h];
    int s = g_rowptr[warp];
    int e = g_rowptr[warp + 1];
    float4 acc = make_float4(0.f, 0.f, 0.f, 0.f);
    float den = 0.f;
    for (int j = s; j < e; j++) {
        int c = g_csrcol[j];
        float a = aln + g_ar[c * 4 + h];
        a = (a >= 0.f) ? a : NEG_SLOPE * a;
        float w = __expf(a);
        den += w;
        float4 v = *(const float4*)(g_xproj + (size_t)c * 128 + lane * 4);
        acc.x += w * v.x; acc.y += w * v.y; acc.z += w * v.z; acc.w += w * v.w;
    }
    float inv = 1.f / (den + 1e-16f);
    float4 bv = *(const float4*)(bias + lane * 4);
    float4 o;
    o.x = acc.x * inv + bv.x;
    o.y = acc.y * inv + bv.y;
    o.z = acc.z * inv + bv.z;
    o.w = acc.w * inv + bv.w;
    *(float4*)(out + (size_t)warp * 128 + lane * 4) = o;
}

// ---------------- launch ----------------------------------------------------
extern "C" void kernel_launch(void* const* d_in, const int* in_sizes, int n_in,
                              void* d_out, int out_size) {
    const float* x    = (const float*)d_in[0];
    const int*   ei   = (const int*)d_in[1];
    const float* W    = (const float*)d_in[2];
    const float* attl = (const float*)d_in[3];
    const float* attr = (const float*)d_in[4];
    const float* bias = (const float*)d_in[5];
    float*       out  = (float*)d_out;

    zero_deg_k<<<(NN + 255) / 256, 256>>>();
    sgemm128_k<<<(NN + 127) / 128, 256>>>(x, W);
    alpha_k<<<(NN + 7) / 8, 256>>>(attl, attr);
    deg_k<<<(EE + 255) / 256, 256>>>(ei);
    const int nb = (NN + 1023) / 1024;
    scan1_k<<<nb, 1024>>>();
    scan2_k<<<1, 128>>>(nb);
    scan3_k<<<(NN + 255) / 256, 256>>>();
    scatter_k<<<(EE + 255) / 256, 256>>>(ei);
    agg_k<<<(NN + 7) / 8, 256>>>(bias, out);
}